// round 8
// baseline (speedup 1.0000x reference)
#include <cuda_runtime.h>
#include <cuda_fp16.h>
#include <cstdint>

// ---------------- problem dims ----------------
#define E_  100
#define B_  1024
#define D_  2048
#define H1_ 512
#define H2_ 256

// ---------------- scratch (__device__ globals; no cudaMalloc allowed) ----
__device__ __half g_xh [(size_t)B_ * D_];          //   4MB
__device__ __half g_w1h[(size_t)E_ * D_ * H1_];    // 210MB
__device__ __half g_w2h[(size_t)E_ * H1_ * H2_];   //  26MB
__device__ __half g_h1h[(size_t)E_ * B_ * H1_];    // 105MB

// ---------------- device helpers ----------------
__device__ __forceinline__ uint32_t smem_u32(const void* p) {
    uint32_t a;
    asm("{ .reg .u64 t; cvta.to.shared.u64 t, %1; cvt.u32.u64 %0, t; }" : "=r"(a) : "l"(p));
    return a;
}
__device__ __forceinline__ void cp_async16(uint32_t s, const void* g) {
    asm volatile("cp.async.cg.shared.global [%0], [%1], 16;" :: "r"(s), "l"(g));
}
__device__ __forceinline__ void cp_commit() {
    asm volatile("cp.async.commit_group;" ::: "memory");
}
__device__ __forceinline__ void ldsm4(uint32_t r[4], uint32_t addr) {
    asm volatile("ldmatrix.sync.aligned.m8n8.x4.shared.b16 {%0,%1,%2,%3}, [%4];"
        : "=r"(r[0]), "=r"(r[1]), "=r"(r[2]), "=r"(r[3]) : "r"(addr));
}
__device__ __forceinline__ void ldsm4t(uint32_t& r0, uint32_t& r1, uint32_t& r2, uint32_t& r3,
                                       uint32_t addr) {
    asm volatile("ldmatrix.sync.aligned.m8n8.x4.trans.shared.b16 {%0,%1,%2,%3}, [%4];"
        : "=r"(r0), "=r"(r1), "=r"(r2), "=r"(r3) : "r"(addr));
}
__device__ __forceinline__ void mma_f16(float c[4], const uint32_t a[4], const uint32_t b[2]) {
    asm volatile(
        "mma.sync.aligned.m16n8k16.row.col.f32.f16.f16.f32 "
        "{%0,%1,%2,%3}, {%4,%5,%6,%7}, {%8,%9}, {%0,%1,%2,%3};"
        : "+f"(c[0]), "+f"(c[1]), "+f"(c[2]), "+f"(c[3])
        : "r"(a[0]), "r"(a[1]), "r"(a[2]), "r"(a[3]), "r"(b[0]), "r"(b[1]));
}

// ---------------- GEMM: 128x128 CTA, 8 warps (4m x 2n), warp tile 32x64 ---
// ~113 regs/thread -> 2 CTAs/SM -> 16 warps/SM (4/SMSP) for latency hiding.
// FUSEL3: layer2 variant - epilogue computes relu(acc+b2) . W3 and atomically
// accumulates per-row dot products into out[b*E+e] (pre-initialized to b3).
#define MT 128
#define NT 128
#define KC 64
#define A_STRIDE 144                 // 64 fp16 = 128B data + 16B pad
#define B_STRIDE 272                 // 128 fp16 = 256B data + 16B pad
#define A_TILE_B (MT * A_STRIDE)     // 18432
#define B_TILE_B (KC * B_STRIDE)     // 17408
#define STAGE_B  (A_TILE_B + B_TILE_B)   // 35840
#define NSTAGE 3
#define SM_TILE_OFF 1024             // bias[128]f32 @0, w3s[128]f32 @512
#define SMEM_TOT (SM_TILE_OFF + NSTAGE * STAGE_B)   // 108544

template <bool FUSEL3>
__global__ void __launch_bounds__(256, 2)
gemm_f16(const __half* __restrict__ A, const __half* __restrict__ Bw,
         const float* __restrict__ bias, __half* __restrict__ C,
         const float* __restrict__ w3, float* __restrict__ outF,
         int nch, int ArowsPerE, int Ntot, unsigned long long strideCe) {
    extern __shared__ __align__(128) char smem[];
    float* bias_s = reinterpret_cast<float*>(smem);
    float* w3_s   = reinterpret_cast<float*>(smem + 512);
    const uint32_t sbase = smem_u32(smem) + SM_TILE_OFF;
    const int tid = threadIdx.x, lane = tid & 31, warp = tid >> 5;
    const int wm = warp >> 1, wn = warp & 1;     // 4m x 2n
    const int e = blockIdx.z, mt = blockIdx.y, nt = blockIdx.x;
    const int n0 = nt * NT;
    const int K = nch * KC;

    if (tid < NT) bias_s[tid] = bias[(size_t)e * Ntot + n0 + tid];
    if (FUSEL3) {
        if (tid >= 128 && tid < 256) w3_s[tid - 128] = w3[(size_t)e * H2_ + n0 + (tid - 128)];
    }

    const char* Ab = (const char*)(A + ((size_t)e * ArowsPerE + (size_t)mt * MT) * K);
    const char* Bb = (const char*)(Bw + (size_t)e * (size_t)K * Ntot + n0);
    const int ldaB = K * 2;
    const int ldbB = Ntot * 2;

    auto load_stage = [&](int s, int c) {
        const uint32_t st = sbase + s * STAGE_B;
        const char* Ac = Ab + c * KC * 2;
        #pragma unroll
        for (int it = 0; it < 4; it++) {
            int q = tid + it * 256;              // 0..1023 (128 rows x 8 segs)
            int r = q >> 3, seg = (q & 7) * 16;
            cp_async16(st + r * A_STRIDE + seg, Ac + (size_t)r * ldaB + seg);
        }
        const char* Bc = Bb + (size_t)(c * KC) * ldbB;
        const uint32_t stb = st + A_TILE_B;
        #pragma unroll
        for (int it = 0; it < 4; it++) {
            int q = tid + it * 256;              // 0..1023 (64 rows x 16 segs)
            int r = q >> 4, seg = (q & 15) * 16;
            cp_async16(stb + r * B_STRIDE + seg, Bc + (size_t)r * ldbB + seg);
        }
    };

    // per-lane ldmatrix offsets (bytes)
    const uint32_t offA = (uint32_t)(lane & 15) * A_STRIDE + (uint32_t)(lane >> 4) * 16;
    const uint32_t offB = (uint32_t)(lane & 15) * B_STRIDE + (uint32_t)(lane >> 4) * 16;
    const uint32_t awoff = (uint32_t)wm * 32 * A_STRIDE + offA;   // warp covers 32 M rows
    const uint32_t bwoff = (uint32_t)wn * 128 + offB;             // warp covers 64 N cols

    float acc[2][8][4];
    #pragma unroll
    for (int i = 0; i < 2; i++)
        #pragma unroll
        for (int j = 0; j < 8; j++)
            #pragma unroll
            for (int r = 0; r < 4; r++) acc[i][j][r] = 0.0f;

    // ---- prologue ----
    load_stage(0, 0); cp_commit();
    load_stage(1, 1); cp_commit();
    asm volatile("cp.async.wait_group 1;" ::: "memory");
    __syncthreads();

    // ---- mainloop ----
    for (int c = 0; c < nch; c++) {
        const uint32_t st = sbase + (c % NSTAGE) * STAGE_B;
        if (c + 2 < nch) { load_stage((c + 2) % NSTAGE, c + 2); cp_commit(); }

        #pragma unroll
        for (int ks = 0; ks < 4; ks++) {
            uint32_t afr[2][4], bfr[8][2];
            const uint32_t sa = st + awoff + (uint32_t)ks * 32;
            ldsm4(afr[0], sa);
            ldsm4(afr[1], sa + 16 * A_STRIDE);
            const uint32_t sb = st + A_TILE_B + bwoff + (uint32_t)ks * (16 * B_STRIDE);
            #pragma unroll
            for (int j2 = 0; j2 < 4; j2++) {
                uint32_t r0, r1, r2, r3;
                ldsm4t(r0, r1, r2, r3, sb + (uint32_t)j2 * 32);
                bfr[j2 * 2][0] = r0;     bfr[j2 * 2][1] = r1;
                bfr[j2 * 2 + 1][0] = r2; bfr[j2 * 2 + 1][1] = r3;
            }
            #pragma unroll
            for (int i = 0; i < 2; i++)
                #pragma unroll
                for (int j = 0; j < 8; j++)
                    mma_f16(acc[i][j], afr[i], bfr[j]);
        }

        if (c + 1 < nch) {
            if (c + 2 < nch) { asm volatile("cp.async.wait_group 1;" ::: "memory"); }
            else             { asm volatile("cp.async.wait_group 0;" ::: "memory"); }
            __syncthreads();
        }
    }

    const int col0 = wn * 64 + (lane & 3) * 2;

    if (FUSEL3) {
        // ---- fused layer-3 epilogue: partial dot over this CTA's 128 cols --
        #pragma unroll
        for (int i = 0; i < 2; i++) {
            #pragma unroll
            for (int rr = 0; rr < 2; rr++) {
                float p = 0.0f;
                #pragma unroll
                for (int j = 0; j < 8; j++) {
                    const int col = col0 + j * 8;
                    float v0 = fmaxf(acc[i][j][rr * 2 + 0] + bias_s[col], 0.0f);
                    float v1 = fmaxf(acc[i][j][rr * 2 + 1] + bias_s[col + 1], 0.0f);
                    p += v0 * w3_s[col] + v1 * w3_s[col + 1];
                }
                p += __shfl_xor_sync(0xFFFFFFFFu, p, 1);
                p += __shfl_xor_sync(0xFFFFFFFFu, p, 2);
                if ((lane & 3) == 0) {
                    const int b = mt * MT + wm * 32 + i * 16 + rr * 8 + (lane >> 2);
                    atomicAdd(&outF[(size_t)b * E_ + e], p);
                }
            }
        }
        return;
    }

    // ---- epilogue: bias + relu, store fp16 ----
    const int mrow0 = mt * MT + wm * 32 + (lane >> 2);
    __half* Ce = C + (size_t)e * strideCe + n0;
    #pragma unroll
    for (int i = 0; i < 2; i++) {
        const size_t r0 = (size_t)(mrow0 + i * 16);
        #pragma unroll
        for (int j = 0; j < 8; j++) {
            const int col = col0 + j * 8;
            const float bx = bias_s[col], by = bias_s[col + 1];
            float v0 = fmaxf(acc[i][j][0] + bx, 0.0f);
            float v1 = fmaxf(acc[i][j][1] + by, 0.0f);
            float v2 = fmaxf(acc[i][j][2] + bx, 0.0f);
            float v3 = fmaxf(acc[i][j][3] + by, 0.0f);
            *reinterpret_cast<__half2*>(Ce + r0 * Ntot + col)       = __floats2half2_rn(v0, v1);
            *reinterpret_cast<__half2*>(Ce + (r0 + 8) * Ntot + col) = __floats2half2_rn(v2, v3);
        }
    }
}

// ---------------- pre-pass: f32 -> f16 (vectorized) ----------------
__global__ void f32_to_f16_kernel(const float4* __restrict__ in, uint2* __restrict__ out,
                                  long n4) {
    long i = blockIdx.x * (long)blockDim.x + threadIdx.x;
    if (i < n4) {
        float4 v = in[i];
        __half2 lo = __floats2half2_rn(v.x, v.y);
        __half2 hi = __floats2half2_rn(v.z, v.w);
        uint2 o;
        o.x = *reinterpret_cast<uint32_t*>(&lo);
        o.y = *reinterpret_cast<uint32_t*>(&hi);
        out[i] = o;
    }
}

// ---------------- out init: out[b*E+e] = b3[e] ----------------
__global__ void out_init_kernel(float* __restrict__ out, const float* __restrict__ b3) {
    int i = blockIdx.x * blockDim.x + threadIdx.x;
    if (i < E_ * B_) out[i] = b3[i % E_];
}

// ---------------- host ----------------
extern "C" void kernel_launch(void* const* d_in, const int* in_sizes, int n_in,
                              void* d_out, int out_size) {
    const float* x  = (const float*)d_in[0];
    const float* W1 = (const float*)d_in[1];
    const float* b1 = (const float*)d_in[2];
    const float* W2 = (const float*)d_in[3];
    const float* b2 = (const float*)d_in[4];
    const float* W3 = (const float*)d_in[5];
    const float* b3 = (const float*)d_in[6];
    float* out = (float*)d_out;

    __half *xh, *w1h, *w2h, *h1h;
    cudaGetSymbolAddress((void**)&xh,  g_xh);
    cudaGetSymbolAddress((void**)&w1h, g_w1h);
    cudaGetSymbolAddress((void**)&w2h, g_w2h);
    cudaGetSymbolAddress((void**)&h1h, g_h1h);

    cudaFuncSetAttribute(gemm_f16<false>, cudaFuncAttributeMaxDynamicSharedMemorySize, SMEM_TOT);
    cudaFuncSetAttribute(gemm_f16<true>,  cudaFuncAttributeMaxDynamicSharedMemorySize, SMEM_TOT);

    // pre-convert to fp16
    {
        long n4x  = (long)B_ * D_ / 4;
        long n4w1 = (long)E_ * D_ * H1_ / 4;
        long n4w2 = (long)E_ * H1_ * H2_ / 4;
        f32_to_f16_kernel<<<(unsigned)((n4x  + 255) / 256), 256>>>((const float4*)x,  (uint2*)xh,  n4x);
        f32_to_f16_kernel<<<(unsigned)((n4w1 + 255) / 256), 256>>>((const float4*)W1, (uint2*)w1h, n4w1);
        f32_to_f16_kernel<<<(unsigned)((n4w2 + 255) / 256), 256>>>((const float4*)W2, (uint2*)w2h, n4w2);
    }

    // init out to b3 (layer2 epilogue accumulates into it)
    out_init_kernel<<<(E_ * B_ + 255) / 256, 256>>>(out, b3);

    // layer 1: per-expert [1024,2048] x [2048,512], relu -> h1 (fp16)
    {
        dim3 grid(H1_ / NT, B_ / MT, E_);   // (4, 8, 100)
        gemm_f16<false><<<grid, 256, SMEM_TOT>>>(
            xh, w1h, b1, h1h, nullptr, nullptr,
            D_ / KC, /*ArowsPerE=*/0, /*Ntot=*/H1_,
            (unsigned long long)B_ * H1_);
    }
    // layer 2 + fused layer 3: per-expert [1024,512] x [512,256], relu,
    // dot with W3 accumulated atomically into out
    {
        dim3 grid(H2_ / NT, B_ / MT, E_);   // (2, 8, 100)
        gemm_f16<true><<<grid, 256, SMEM_TOT>>>(
            h1h, w2h, b2, nullptr, W3, out,
            H1_ / KC, /*ArowsPerE=*/B_, /*Ntot=*/H2_,
            0ULL);
    }
}

// round 9
// speedup vs baseline: 1.0993x; 1.0993x over previous
#include <cuda_runtime.h>
#include <cuda_fp16.h>
#include <cstdint>

// ---------------- problem dims ----------------
#define E_  100
#define B_  1024
#define D_  2048
#define H1_ 512
#define H2_ 256

// ---------------- scratch (__device__ globals; no cudaMalloc allowed) ----
__device__ __half g_xh [(size_t)B_ * D_];          //   4MB
__device__ __half g_w1h[(size_t)E_ * D_ * H1_];    // 210MB
__device__ __half g_w2h[(size_t)E_ * H1_ * H2_];   //  26MB
__device__ __half g_h1h[(size_t)E_ * B_ * H1_];    // 105MB

// ---------------- device helpers ----------------
__device__ __forceinline__ uint32_t smem_u32(const void* p) {
    uint32_t a;
    asm("{ .reg .u64 t; cvta.to.shared.u64 t, %1; cvt.u32.u64 %0, t; }" : "=r"(a) : "l"(p));
    return a;
}
__device__ __forceinline__ void cp_async16(uint32_t s, const void* g) {
    asm volatile("cp.async.cg.shared.global [%0], [%1], 16;" :: "r"(s), "l"(g));
}
__device__ __forceinline__ void cp_commit() {
    asm volatile("cp.async.commit_group;" ::: "memory");
}
__device__ __forceinline__ void ldsm4(uint32_t r[4], uint32_t addr) {
    asm volatile("ldmatrix.sync.aligned.m8n8.x4.shared.b16 {%0,%1,%2,%3}, [%4];"
        : "=r"(r[0]), "=r"(r[1]), "=r"(r[2]), "=r"(r[3]) : "r"(addr));
}
__device__ __forceinline__ void ldsm4t(uint32_t& r0, uint32_t& r1, uint32_t& r2, uint32_t& r3,
                                       uint32_t addr) {
    asm volatile("ldmatrix.sync.aligned.m8n8.x4.trans.shared.b16 {%0,%1,%2,%3}, [%4];"
        : "=r"(r0), "=r"(r1), "=r"(r2), "=r"(r3) : "r"(addr));
}
__device__ __forceinline__ void mma_f16(float c[4], const uint32_t a[4], const uint32_t b[2]) {
    asm volatile(
        "mma.sync.aligned.m16n8k16.row.col.f32.f16.f16.f32 "
        "{%0,%1,%2,%3}, {%4,%5,%6,%7}, {%8,%9}, {%0,%1,%2,%3};"
        : "+f"(c[0]), "+f"(c[1]), "+f"(c[2]), "+f"(c[3])
        : "r"(a[0]), "r"(a[1]), "r"(a[2]), "r"(a[3]), "r"(b[0]), "r"(b[1]));
}

// ---------------- GEMM: 128x128 CTA, 4 warps (2m x 2n), warp tile 64x64 ---
// R7-proven geometry: best bytes-per-MMA ratio (128B/mma), 2 CTAs/SM.
// FUSEL3: epilogue computes relu(acc+bias) . w3 per row and atomically
// accumulates into outF[b*E+e] (pre-initialized to b3) instead of storing C.
#define MT 128
#define NT 128
#define KC 64
#define A_STRIDE 144                 // 64 fp16 = 128B data + 16B pad
#define B_STRIDE 272                 // 128 fp16 = 256B data + 16B pad
#define A_TILE_B (MT * A_STRIDE)     // 18432
#define B_TILE_B (KC * B_STRIDE)     // 17408
#define STAGE_B  (A_TILE_B + B_TILE_B)   // 35840
#define NSTAGE 3
#define SM_TILE_OFF 1024             // bias[128]f32 @0, w3_s[128]f32 @512
#define SMEM_TOT (SM_TILE_OFF + NSTAGE * STAGE_B)   // 108544

template <bool FUSEL3>
__global__ void __launch_bounds__(128, 2)
gemm_f16(const __half* __restrict__ A, const __half* __restrict__ Bw,
         const float* __restrict__ bias, __half* __restrict__ C,
         const float* __restrict__ w3, float* __restrict__ outF,
         int nch, int ArowsPerE, int Ntot, unsigned long long strideCe) {
    extern __shared__ __align__(128) char smem[];
    float* bias_s = reinterpret_cast<float*>(smem);
    float* w3_s   = reinterpret_cast<float*>(smem + 512);
    const uint32_t sbase = smem_u32(smem) + SM_TILE_OFF;
    const int tid = threadIdx.x, lane = tid & 31, warp = tid >> 5;
    const int wm = warp >> 1, wn = warp & 1;
    const int e = blockIdx.z, mt = blockIdx.y, nt = blockIdx.x;
    const int n0 = nt * NT;
    const int K = nch * KC;

    if (tid < NT) {
        bias_s[tid] = bias[(size_t)e * Ntot + n0 + tid];
        if (FUSEL3) w3_s[tid] = w3[(size_t)e * H2_ + n0 + tid];
    }

    const char* Ab = (const char*)(A + ((size_t)e * ArowsPerE + (size_t)mt * MT) * K);
    const char* Bb = (const char*)(Bw + (size_t)e * (size_t)K * Ntot + n0);
    const int ldaB = K * 2;
    const int ldbB = Ntot * 2;

    auto load_stage = [&](int s, int c) {
        const uint32_t st = sbase + s * STAGE_B;
        const char* Ac = Ab + c * KC * 2;
        #pragma unroll
        for (int it = 0; it < 8; it++) {
            int q = tid + it * 128;              // 0..1023 (128 rows x 8 segs)
            int r = q >> 3, seg = (q & 7) * 16;
            cp_async16(st + r * A_STRIDE + seg, Ac + (size_t)r * ldaB + seg);
        }
        const char* Bc = Bb + (size_t)(c * KC) * ldbB;
        const uint32_t stb = st + A_TILE_B;
        #pragma unroll
        for (int it = 0; it < 8; it++) {
            int q = tid + it * 128;              // 0..1023 (64 rows x 16 segs)
            int r = q >> 4, seg = (q & 15) * 16;
            cp_async16(stb + r * B_STRIDE + seg, Bc + (size_t)r * ldbB + seg);
        }
    };

    // per-lane ldmatrix offsets (bytes)
    const uint32_t offA = (uint32_t)(lane & 15) * A_STRIDE + (uint32_t)(lane >> 4) * 16;
    const uint32_t offB = (uint32_t)(lane & 15) * B_STRIDE + (uint32_t)(lane >> 4) * 16;
    const uint32_t awoff = (uint32_t)wm * 64 * A_STRIDE + offA;
    const uint32_t bwoff = (uint32_t)wn * 128 + offB;         // wn*64 cols * 2B

    // double-buffered fragments: A 4 m16-tiles, B 8 n8-blocks
    uint32_t afr[2][4][4], bfr[2][8][2];

    auto prefetch = [&](uint32_t st, int ks, int buf) {
        const uint32_t sa = st + awoff + (uint32_t)ks * 32;
        #pragma unroll
        for (int i = 0; i < 4; i++)
            ldsm4(afr[buf][i], sa + (uint32_t)i * (16 * A_STRIDE));
        const uint32_t sb = st + A_TILE_B + bwoff + (uint32_t)ks * (16 * B_STRIDE);
        #pragma unroll
        for (int j2 = 0; j2 < 4; j2++) {
            uint32_t r0, r1, r2, r3;
            ldsm4t(r0, r1, r2, r3, sb + (uint32_t)j2 * 32);
            bfr[buf][j2 * 2][0] = r0;     bfr[buf][j2 * 2][1] = r1;
            bfr[buf][j2 * 2 + 1][0] = r2; bfr[buf][j2 * 2 + 1][1] = r3;
        }
    };

    float acc[4][8][4];
    #pragma unroll
    for (int i = 0; i < 4; i++)
        #pragma unroll
        for (int j = 0; j < 8; j++)
            #pragma unroll
            for (int r = 0; r < 4; r++) acc[i][j][r] = 0.0f;

    // ---- prologue ----
    load_stage(0, 0); cp_commit();
    load_stage(1, 1); cp_commit();
    asm volatile("cp.async.wait_group 1;" ::: "memory");
    __syncthreads();
    prefetch(sbase, 0, 0);

    // ---- mainloop ----
    for (int c = 0; c < nch; c++) {
        const uint32_t st = sbase + (c % NSTAGE) * STAGE_B;
        if (c + 2 < nch) { load_stage((c + 2) % NSTAGE, c + 2); cp_commit(); }

        #pragma unroll
        for (int ks = 0; ks < 4; ks++) {
            const int cur = ks & 1;
            if (ks < 3) prefetch(st, ks + 1, cur ^ 1);
            #pragma unroll
            for (int i = 0; i < 4; i++)
                #pragma unroll
                for (int j = 0; j < 8; j++)
                    mma_f16(acc[i][j], afr[cur][i], bfr[cur][j]);
        }

        if (c + 1 < nch) {
            if (c + 2 < nch) { asm volatile("cp.async.wait_group 1;" ::: "memory"); }
            else             { asm volatile("cp.async.wait_group 0;" ::: "memory"); }
            __syncthreads();
            prefetch(sbase + ((c + 1) % NSTAGE) * STAGE_B, 0, 0);
        }
    }

    const int col0 = wn * 64 + (lane & 3) * 2;

    if (FUSEL3) {
        // ---- fused layer-3 epilogue: partial dot over this CTA's 128 cols --
        #pragma unroll
        for (int i = 0; i < 4; i++) {
            #pragma unroll
            for (int rr = 0; rr < 2; rr++) {
                float p = 0.0f;
                #pragma unroll
                for (int j = 0; j < 8; j++) {
                    const int col = col0 + j * 8;
                    float v0 = fmaxf(acc[i][j][rr * 2 + 0] + bias_s[col], 0.0f);
                    float v1 = fmaxf(acc[i][j][rr * 2 + 1] + bias_s[col + 1], 0.0f);
                    p += v0 * w3_s[col] + v1 * w3_s[col + 1];
                }
                p += __shfl_xor_sync(0xFFFFFFFFu, p, 1);
                p += __shfl_xor_sync(0xFFFFFFFFu, p, 2);
                if ((lane & 3) == 0) {
                    const int b = mt * MT + wm * 64 + i * 16 + rr * 8 + (lane >> 2);
                    atomicAdd(&outF[(size_t)b * E_ + e], p);
                }
            }
        }
        return;
    }

    // ---- epilogue: bias + relu, store fp16 ----
    const int mrow0 = mt * MT + wm * 64 + (lane >> 2);
    __half* Ce = C + (size_t)e * strideCe + n0;
    #pragma unroll
    for (int i = 0; i < 4; i++) {
        const size_t r0 = (size_t)(mrow0 + i * 16);
        #pragma unroll
        for (int j = 0; j < 8; j++) {
            const int col = col0 + j * 8;
            const float bx = bias_s[col], by = bias_s[col + 1];
            float v0 = fmaxf(acc[i][j][0] + bx, 0.0f);
            float v1 = fmaxf(acc[i][j][1] + by, 0.0f);
            float v2 = fmaxf(acc[i][j][2] + bx, 0.0f);
            float v3 = fmaxf(acc[i][j][3] + by, 0.0f);
            *reinterpret_cast<__half2*>(Ce + r0 * Ntot + col)       = __floats2half2_rn(v0, v1);
            *reinterpret_cast<__half2*>(Ce + (r0 + 8) * Ntot + col) = __floats2half2_rn(v2, v3);
        }
    }
}

// ---------------- pre-pass: f32 -> f16 (vectorized) ----------------
__global__ void f32_to_f16_kernel(const float4* __restrict__ in, uint2* __restrict__ out,
                                  long n4) {
    long i = blockIdx.x * (long)blockDim.x + threadIdx.x;
    if (i < n4) {
        float4 v = in[i];
        __half2 lo = __floats2half2_rn(v.x, v.y);
        __half2 hi = __floats2half2_rn(v.z, v.w);
        uint2 o;
        o.x = *reinterpret_cast<uint32_t*>(&lo);
        o.y = *reinterpret_cast<uint32_t*>(&hi);
        out[i] = o;
    }
}

// ---------------- out init: out[b*E+e] = b3[e] ----------------
__global__ void out_init_kernel(float* __restrict__ out, const float* __restrict__ b3) {
    int i = blockIdx.x * blockDim.x + threadIdx.x;
    if (i < E_ * B_) out[i] = b3[i % E_];
}

// ---------------- host ----------------
extern "C" void kernel_launch(void* const* d_in, const int* in_sizes, int n_in,
                              void* d_out, int out_size) {
    const float* x  = (const float*)d_in[0];
    const float* W1 = (const float*)d_in[1];
    const float* b1 = (const float*)d_in[2];
    const float* W2 = (const float*)d_in[3];
    const float* b2 = (const float*)d_in[4];
    const float* W3 = (const float*)d_in[5];
    const float* b3 = (const float*)d_in[6];
    float* out = (float*)d_out;

    __half *xh, *w1h, *w2h, *h1h;
    cudaGetSymbolAddress((void**)&xh,  g_xh);
    cudaGetSymbolAddress((void**)&w1h, g_w1h);
    cudaGetSymbolAddress((void**)&w2h, g_w2h);
    cudaGetSymbolAddress((void**)&h1h, g_h1h);

    cudaFuncSetAttribute(gemm_f16<false>, cudaFuncAttributeMaxDynamicSharedMemorySize, SMEM_TOT);
    cudaFuncSetAttribute(gemm_f16<true>,  cudaFuncAttributeMaxDynamicSharedMemorySize, SMEM_TOT);

    // pre-convert to fp16
    {
        long n4x  = (long)B_ * D_ / 4;
        long n4w1 = (long)E_ * D_ * H1_ / 4;
        long n4w2 = (long)E_ * H1_ * H2_ / 4;
        f32_to_f16_kernel<<<(unsigned)((n4x  + 255) / 256), 256>>>((const float4*)x,  (uint2*)xh,  n4x);
        f32_to_f16_kernel<<<(unsigned)((n4w1 + 255) / 256), 256>>>((const float4*)W1, (uint2*)w1h, n4w1);
        f32_to_f16_kernel<<<(unsigned)((n4w2 + 255) / 256), 256>>>((const float4*)W2, (uint2*)w2h, n4w2);
    }

    // init out to b3 (layer2 fused epilogue accumulates into it)
    out_init_kernel<<<(E_ * B_ + 255) / 256, 256>>>(out, b3);

    // layer 1: per-expert [1024,2048] x [2048,512], relu -> h1 (fp16)
    {
        dim3 grid(H1_ / NT, B_ / MT, E_);   // (4, 8, 100)
        gemm_f16<false><<<grid, 128, SMEM_TOT>>>(
            xh, w1h, b1, h1h, nullptr, nullptr,
            D_ / KC, /*ArowsPerE=*/0, /*Ntot=*/H1_,
            (unsigned long long)B_ * H1_);
    }
    // layer 2 + fused layer 3: per-expert [1024,512] x [512,256], relu,
    // dot with W3 accumulated atomically into out
    {
        dim3 grid(H2_ / NT, B_ / MT, E_);   // (2, 8, 100)
        gemm_f16<true><<<grid, 128, SMEM_TOT>>>(
            h1h, w2h, b2, nullptr, W3, out,
            H1_ / KC, /*ArowsPerE=*/B_, /*Ntot=*/H2_,
            0ULL);
    }
}